// round 7
// baseline (speedup 1.0000x reference)
#include <cuda_runtime.h>
#include <math.h>

typedef unsigned long long ull;

#define NMAX 524288

// ---------------- device-global scratch ----------------
__device__ __align__(16) float g_T[92 * NMAX];     // ifrd transposed: [feat][pt]
__device__ __align__(16) float g_voxT[8 * NMAX];   // vox transposed

// Transposed weight layout (floats). wt[k*J + j], j contiguous.
#define OFF_GLOB_WT 0       // [57][32]
#define OFF_GLOB_B  1824    // [32]
#define OFF_AGGW    1856    // [32]
#define OFF_FC_WT   1888    // [32][16]
#define OFF_FC_B    2400    // [16]
#define OFF_LR0_WT  2416    // [24][64]
#define OFF_LR0_B   3952    // [64]
#define OFF_SIGMA_W 4016    // [64]
#define OFF_COL1_WT 4080    // [111][64]
#define OFF_COL1_B  11184   // [64]
#define OFF_COL2_W  11248   // [64]
#define OFF_VIEW_WT 11312   // [4][19]
#define OFF_VIEW_B  11388   // [19]
#define OFF_SC      11407   // aggw_b, sigma_b, col2_b
#define WT_TOTAL    11410

__device__ __align__(16) float g_wt[WT_TOTAL + 2];

// ---------------- packed f32x2 helpers ----------------
__device__ __forceinline__ ull ffma2(ull a, ull b, ull c) {
    ull d; asm("fma.rn.f32x2 %0, %1, %2, %3;" : "=l"(d) : "l"(a), "l"(b), "l"(c));
    return d;
}
__device__ __forceinline__ ull fmul2(ull a, ull b) {
    ull d; asm("mul.rn.f32x2 %0, %1, %2;" : "=l"(d) : "l"(a), "l"(b));
    return d;
}
__device__ __forceinline__ ull fadd2(ull a, ull b) {
    ull d; asm("add.rn.f32x2 %0, %1, %2;" : "=l"(d) : "l"(a), "l"(b));
    return d;
}
__device__ __forceinline__ ull pack2(float x) {
    ull r; asm("mov.b64 %0, {%1, %1};" : "=l"(r) : "r"(__float_as_uint(x)));
    return r;
}
__device__ __forceinline__ ull pack2f(float a, float b) {
    ull r; asm("mov.b64 %0, {%1, %2};" : "=l"(r)
               : "r"(__float_as_uint(a)), "r"(__float_as_uint(b)));
    return r;
}
__device__ __forceinline__ float2 unpack2(ull v) {
    unsigned lo, hi; asm("mov.b64 {%0, %1}, %2;" : "=r"(lo), "=r"(hi) : "l"(v));
    return make_float2(__uint_as_float(lo), __uint_as_float(hi));
}
__device__ __forceinline__ ull relu2(ull v) {
    float2 f = unpack2(v);
    return pack2f(fmaxf(f.x, 0.0f), fmaxf(f.y, 0.0f));
}
__device__ __forceinline__ float halfOf(ull v, int hi) {
    float2 f = unpack2(v);
    return hi ? f.y : f.x;
}

// acc is ull[16] (32 j outputs, j-packed). xx = pack2(scalar).
#define ACC16(acc, xx, woff)                                                     \
    {                                                                            \
        const ulonglong2* w2 = reinterpret_cast<const ulonglong2*>(sw + (woff)); \
        _Pragma("unroll")                                                        \
        for (int q = 0; q < 8; q++) {                                            \
            ulonglong2 ww = w2[q];                                               \
            acc[2 * q]     = ffma2(ww.x, (xx), acc[2 * q]);                      \
            acc[2 * q + 1] = ffma2(ww.y, (xx), acc[2 * q + 1]);                  \
        }                                                                        \
    }
#define ACC8(acc, xx, woff)                                                      \
    {                                                                            \
        const ulonglong2* w2 = reinterpret_cast<const ulonglong2*>(sw + (woff)); \
        _Pragma("unroll")                                                        \
        for (int q = 0; q < 4; q++) {                                            \
            ulonglong2 ww = w2[q];                                               \
            acc[2 * q]     = ffma2(ww.x, (xx), acc[2 * q]);                      \
            acc[2 * q + 1] = ffma2(ww.y, (xx), acc[2 * q + 1]);                  \
        }                                                                        \
    }
#define LOADB16(acc, off)                                                        \
    {                                                                            \
        const ulonglong2* b2 = reinterpret_cast<const ulonglong2*>(sw + (off));  \
        _Pragma("unroll")                                                        \
        for (int q = 0; q < 8; q++) {                                            \
            ulonglong2 bb = b2[q];                                               \
            acc[2 * q] = bb.x; acc[2 * q + 1] = bb.y;                            \
        }                                                                        \
    }
#define LOADB8(acc, off)                                                         \
    {                                                                            \
        const ulonglong2* b2 = reinterpret_cast<const ulonglong2*>(sw + (off));  \
        _Pragma("unroll")                                                        \
        for (int q = 0; q < 4; q++) {                                            \
            ulonglong2 bb = b2[q];                                               \
            acc[2 * q] = bb.x; acc[2 * q + 1] = bb.y;                            \
        }                                                                        \
    }

// ---------------- prep: transpose weights into g_wt ----------------
__global__ void prep_kernel(const float* __restrict__ view_w, const float* __restrict__ view_b,
                            const float* __restrict__ glob_w, const float* __restrict__ glob_b,
                            const float* __restrict__ aggw_w, const float* __restrict__ aggw_b,
                            const float* __restrict__ fc_w,   const float* __restrict__ fc_b,
                            const float* __restrict__ lr0_w,  const float* __restrict__ lr0_b,
                            const float* __restrict__ sigma_w,const float* __restrict__ sigma_b,
                            const float* __restrict__ col1_w, const float* __restrict__ col1_b,
                            const float* __restrict__ col2_w, const float* __restrict__ col2_b) {
    const int t = threadIdx.x;
    const int bs = blockDim.x;
    for (int idx = t; idx < 32 * 57; idx += bs) {
        int j = idx / 57, k = idx % 57;
        g_wt[OFF_GLOB_WT + k * 32 + j] = glob_w[idx];
    }
    for (int idx = t; idx < 32; idx += bs) {
        g_wt[OFF_GLOB_B + idx] = glob_b[idx];
        g_wt[OFF_AGGW + idx]   = aggw_w[idx];
    }
    for (int idx = t; idx < 16 * 32; idx += bs) {
        int j = idx / 32, k = idx % 32;
        g_wt[OFF_FC_WT + k * 16 + j] = fc_w[idx];
    }
    for (int idx = t; idx < 16; idx += bs) g_wt[OFF_FC_B + idx] = fc_b[idx];
    for (int idx = t; idx < 64 * 24; idx += bs) {
        int j = idx / 24, k = idx % 24;
        g_wt[OFF_LR0_WT + k * 64 + j] = lr0_w[idx];
    }
    for (int idx = t; idx < 64; idx += bs) {
        g_wt[OFF_LR0_B + idx]   = lr0_b[idx];
        g_wt[OFF_SIGMA_W + idx] = sigma_w[idx];
        g_wt[OFF_COL1_B + idx]  = col1_b[idx];
        g_wt[OFF_COL2_W + idx]  = col2_w[idx];
    }
    for (int idx = t; idx < 64 * 111; idx += bs) {
        int j = idx / 111, k = idx % 111;
        g_wt[OFF_COL1_WT + k * 64 + j] = col1_w[idx];
    }
    for (int idx = t; idx < 76; idx += bs) {
        int j = idx / 4, k = idx % 4;
        g_wt[OFF_VIEW_WT + k * 19 + j] = view_w[idx];
    }
    for (int idx = t; idx < 19; idx += bs) g_wt[OFF_VIEW_B + idx] = view_b[idx];
    if (t == 0) {
        g_wt[OFF_SC + 0] = aggw_b[0];
        g_wt[OFF_SC + 1] = sigma_b[0];
        g_wt[OFF_SC + 2] = col2_b[0];
    }
}

// ---------------- input transpose: [rows][cols] -> [cols][rows] ----------------
__global__ void transpose_kernel(const float* __restrict__ in, float* __restrict__ outp,
                                 int rows, int cols) {
    __shared__ float tile[32][33];
    const int c0 = blockIdx.y * 32;
    const long long r0 = (long long)blockIdx.x * 32;
    const int tx = threadIdx.x, ty = threadIdx.y;
#pragma unroll
    for (int i = 0; i < 32; i += 8) {
        long long r = r0 + ty + i;
        int c = c0 + tx;
        if (r < rows && c < cols) tile[ty + i][tx] = in[r * cols + c];
    }
    __syncthreads();
#pragma unroll
    for (int i = 0; i < 32; i += 8) {
        int c = c0 + ty + i;
        long long r = r0 + tx;
        if (r < rows && c < cols) outp[(size_t)c * rows + r] = tile[tx][ty + i];
    }
}

// ---------------- main kernel ----------------
#define TB 128
#define PTSB 256   // points per block (P=2)

__global__ void __launch_bounds__(TB)
nerf_main(float* __restrict__ out, int N) {
    extern __shared__ char dynsmem[];
    ull* sbuf = (ull*)dynsmem;                 // 32*256 ull = 64KB thread-private scratch
    __shared__ __align__(16) float sw[WT_TOTAL + 2];

    // stage weights (coalesced from pre-transposed g_wt)
    for (int idx = threadIdx.x; idx < WT_TOTAL; idx += TB) sw[idx] = g_wt[idx];
    __syncthreads();

    const int t = threadIdx.x;
    const int base = blockIdx.x * PTSB;
    const int pt0 = base + t;
    const int pt1 = base + 128 + t;
    const bool v0 = pt0 < N;
    const bool v1 = pt1 < N;
    const size_t p0 = (size_t)(v0 ? pt0 : 0);
    const size_t p1 = (size_t)(v1 ? pt1 : 0);
    const size_t sN = (size_t)N;

#define IN2(f) pack2f(g_T[(size_t)(f) * sN + p0], g_T[(size_t)(f) * sN + p1])

    // ============ Phase A: dirs, stats, gf_base (spilled to sbuf) ============
    ull dirs[4][4];
#pragma unroll
    for (int s = 0; s < 4; s++)
#pragma unroll
        for (int c = 0; c < 4; c++) dirs[s][c] = IN2(s * 23 + 19 + c);

    {
        ull gfb0[16], gfb1[16];
        LOADB16(gfb0, OFF_GLOB_B);
#pragma unroll
        for (int q = 0; q < 16; q++) gfb1[q] = gfb0[q];

        const ull c4n = pack2(-4.0f);
        const ull third = pack2(1.0f / 3.0f);
        const ull quarter = pack2(0.25f);

#pragma unroll 2
        for (int k = 0; k < 19; k++) {
            ull sum2 = 0ull, sq2 = 0ull;
#pragma unroll
            for (int s = 0; s < 4; s++) {
                ull a = pack2(sw[OFF_VIEW_B + k]);
                a = ffma2(pack2(sw[OFF_VIEW_WT + 0 * 19 + k]), dirs[s][0], a);
                a = ffma2(pack2(sw[OFF_VIEW_WT + 1 * 19 + k]), dirs[s][1], a);
                a = ffma2(pack2(sw[OFF_VIEW_WT + 2 * 19 + k]), dirs[s][2], a);
                a = ffma2(pack2(sw[OFF_VIEW_WT + 3 * 19 + k]), dirs[s][3], a);
                a = relu2(a);
                ull f = fadd2(IN2(s * 23 + k), a);
                sum2 = fadd2(sum2, f);
                sq2 = ffma2(f, f, sq2);
            }
            ull m2 = fmul2(sum2, quarter);
            ull vr2 = fmul2(ffma2(m2, fmul2(m2, c4n), sq2), third);
            float2 mf = unpack2(m2), vf = unpack2(vr2);

            ull x0 = pack2(vf.x), x1 = pack2(vf.y);
            ACC16(gfb0, x0, OFF_GLOB_WT + (19 + k) * 32);
            ACC16(gfb1, x1, OFF_GLOB_WT + (19 + k) * 32);
            x0 = pack2(mf.x); x1 = pack2(mf.y);
            ACC16(gfb0, x0, OFF_GLOB_WT + (38 + k) * 32);
            ACC16(gfb1, x1, OFF_GLOB_WT + (38 + k) * 32);
        }
        // spill gf_base to thread-private smem scratch
#pragma unroll
        for (int q = 0; q < 16; q++) {
            sbuf[q * 256 + t] = gfb0[q];
            sbuf[q * 256 + 128 + t] = gfb1[q];
        }
    }

    // ============ Phase B: per-view glob + online softmax agg ============
    ull num0[16], num1[16];
#pragma unroll
    for (int q = 0; q < 16; q++) { num0[q] = 0ull; num1[q] = 0ull; }
    float dsum0 = 0.0f, dsum1 = 0.0f, mmax0 = -1e30f, mmax1 = -1e30f;
    const float aggb = sw[OFF_SC + 0];

#pragma unroll
    for (int s = 0; s < 4; s++) {
        ull gf0[16], gf1[16];
#pragma unroll
        for (int q = 0; q < 16; q++) {
            gf0[q] = sbuf[q * 256 + t];
            gf1[q] = sbuf[q * 256 + 128 + t];
        }
#pragma unroll 2
        for (int k = 0; k < 19; k++) {
            ull a = pack2(sw[OFF_VIEW_B + k]);
            a = ffma2(pack2(sw[OFF_VIEW_WT + 0 * 19 + k]), dirs[s][0], a);
            a = ffma2(pack2(sw[OFF_VIEW_WT + 1 * 19 + k]), dirs[s][1], a);
            a = ffma2(pack2(sw[OFF_VIEW_WT + 2 * 19 + k]), dirs[s][2], a);
            a = ffma2(pack2(sw[OFF_VIEW_WT + 3 * 19 + k]), dirs[s][3], a);
            a = relu2(a);
            ull f = fadd2(IN2(s * 23 + k), a);
            float2 fi = unpack2(f);
            ull x0 = pack2(fi.x), x1 = pack2(fi.y);
            ACC16(gf0, x0, OFF_GLOB_WT + k * 32);
            ACC16(gf1, x1, OFF_GLOB_WT + k * 32);
        }
        // relu + agg dot (j-packed)
        ull la0 = 0ull, la1 = 0ull;
        {
            const ulonglong2* aw = reinterpret_cast<const ulonglong2*>(sw + OFF_AGGW);
#pragma unroll
            for (int q2 = 0; q2 < 8; q2++) {
                ulonglong2 a2 = aw[q2];
                gf0[2 * q2] = relu2(gf0[2 * q2]);
                gf0[2 * q2 + 1] = relu2(gf0[2 * q2 + 1]);
                gf1[2 * q2] = relu2(gf1[2 * q2]);
                gf1[2 * q2 + 1] = relu2(gf1[2 * q2 + 1]);
                la0 = ffma2(a2.x, gf0[2 * q2], la0);
                la0 = ffma2(a2.y, gf0[2 * q2 + 1], la0);
                la1 = ffma2(a2.x, gf1[2 * q2], la1);
                la1 = ffma2(a2.y, gf1[2 * q2 + 1], la1);
            }
        }
        float2 lf0 = unpack2(la0), lf1 = unpack2(la1);
        float l0 = fmaxf(lf0.x + lf0.y + aggb, 0.0f);
        float l1 = fmaxf(lf1.x + lf1.y + aggb, 0.0f);

        if (l0 > mmax0) {
            float c = __expf(mmax0 - l0); ull c2 = pack2(c);
            dsum0 *= c;
#pragma unroll
            for (int q = 0; q < 16; q++) num0[q] = fmul2(num0[q], c2);
            mmax0 = l0;
        }
        {
            float e = __expf(l0 - mmax0); dsum0 += e; ull e2 = pack2(e);
#pragma unroll
            for (int q = 0; q < 16; q++) num0[q] = ffma2(gf0[q], e2, num0[q]);
        }
        if (l1 > mmax1) {
            float c = __expf(mmax1 - l1); ull c2 = pack2(c);
            dsum1 *= c;
#pragma unroll
            for (int q = 0; q < 16; q++) num1[q] = fmul2(num1[q], c2);
            mmax1 = l1;
        }
        {
            float e = __expf(l1 - mmax1); dsum1 += e; ull e2 = pack2(e);
#pragma unroll
            for (int q = 0; q < 16; q++) num1[q] = ffma2(gf1[q], e2, num1[q]);
        }
    }

    // ============ fc: 32 -> 16, build vif[2][24] ============
    float vif0[24], vif1[24];
    {
        float inv0 = 1.0f / dsum0, inv1 = 1.0f / dsum1;
        ull fa0[8], fa1[8];
        LOADB8(fa0, OFF_FC_B);
#pragma unroll
        for (int q = 0; q < 8; q++) fa1[q] = fa0[q];
#pragma unroll 4
        for (int k = 0; k < 32; k++) {
            ull x0 = pack2(halfOf(num0[k >> 1], k & 1) * inv0);
            ull x1 = pack2(halfOf(num1[k >> 1], k & 1) * inv1);
            ACC8(fa0, x0, OFF_FC_WT + k * 16);
            ACC8(fa1, x1, OFF_FC_WT + k * 16);
        }
#pragma unroll
        for (int c = 0; c < 8; c++) {
            vif0[c] = g_voxT[(size_t)c * sN + p0];
            vif1[c] = g_voxT[(size_t)c * sN + p1];
        }
#pragma unroll
        for (int j = 0; j < 16; j++) {
            vif0[8 + j] = fmaxf(halfOf(fa0[j >> 1], j & 1), 0.0f);
            vif1[8 + j] = fmaxf(halfOf(fa1[j >> 1], j & 1), 0.0f);
        }
    }

    // ============ lr0: 24 -> 64 (two j-tiles), relu, sigma partial, x->sbuf ====
    ull siga0 = 0ull, siga1 = 0ull;
#pragma unroll
    for (int jt = 0; jt < 2; jt++) {
        const int j0 = jt * 32;
        ull xa0[16], xa1[16];
        LOADB16(xa0, OFF_LR0_B + j0);
#pragma unroll
        for (int q = 0; q < 16; q++) xa1[q] = xa0[q];
#pragma unroll 4
        for (int k = 0; k < 24; k++) {
            ull x0 = pack2(vif0[k]);
            ull x1 = pack2(vif1[k]);
            ACC16(xa0, x0, OFF_LR0_WT + k * 64 + j0);
            ACC16(xa1, x1, OFF_LR0_WT + k * 64 + j0);
        }
        const ulonglong2* swg = reinterpret_cast<const ulonglong2*>(sw + OFF_SIGMA_W + j0);
#pragma unroll
        for (int q2 = 0; q2 < 8; q2++) {
            ulonglong2 w = swg[q2];
            ull r0a = relu2(xa0[2 * q2]);
            ull r0b = relu2(xa0[2 * q2 + 1]);
            ull r1a = relu2(xa1[2 * q2]);
            ull r1b = relu2(xa1[2 * q2 + 1]);
            siga0 = ffma2(w.x, r0a, siga0);
            siga0 = ffma2(w.y, r0b, siga0);
            siga1 = ffma2(w.x, r1a, siga1);
            siga1 = ffma2(w.y, r1b, siga1);
            sbuf[(jt * 16 + 2 * q2) * 256 + t] = r0a;
            sbuf[(jt * 16 + 2 * q2 + 1) * 256 + t] = r0b;
            sbuf[(jt * 16 + 2 * q2) * 256 + 128 + t] = r1a;
            sbuf[(jt * 16 + 2 * q2 + 1) * 256 + 128 + t] = r1b;
        }
    }
    float sig0, sig1;
    {
        float2 s0 = unpack2(siga0), s1 = unpack2(siga1);
        float l0 = s0.x + s0.y + sw[OFF_SC + 1];
        float l1 = s1.x + s1.y + sw[OFF_SC + 1];
        sig0 = (l0 > 20.0f) ? l0 : log1pf(expf(l0));
        sig1 = (l1 > 20.0f) ? l1 : log1pf(expf(l1));
    }

    // ============ col1 (j-tiled) + col2 partial logits ============
    ull lacc0[4], lacc1[4];
#pragma unroll
    for (int s = 0; s < 4; s++) { lacc0[s] = 0ull; lacc1[s] = 0ull; }
    const float* sbf = (const float*)sbuf;  // x as scalars: idx = (k>>1)*512 + ptl*2 + (k&1)

#pragma unroll
    for (int jt = 0; jt < 2; jt++) {
        const int j0 = jt * 32;
        ull ba0[16], ba1[16];
        LOADB16(ba0, OFF_COL1_B + j0);
#pragma unroll
        for (int q = 0; q < 16; q++) ba1[q] = ba0[q];
#pragma unroll 2
        for (int k = 0; k < 64; k++) {
            float xv0 = sbf[(k >> 1) * 512 + t * 2 + (k & 1)];
            float xv1 = sbf[(k >> 1) * 512 + (128 + t) * 2 + (k & 1)];
            ull x0 = pack2(xv0);
            ull x1 = pack2(xv1);
            ACC16(ba0, x0, OFF_COL1_WT + k * 64 + j0);
            ACC16(ba1, x1, OFF_COL1_WT + k * 64 + j0);
        }
#pragma unroll 2
        for (int k = 0; k < 24; k++) {
            ull x0 = pack2(vif0[k]);
            ull x1 = pack2(vif1[k]);
            ACC16(ba0, x0, OFF_COL1_WT + (64 + k) * 64 + j0);
            ACC16(ba1, x1, OFF_COL1_WT + (64 + k) * 64 + j0);
        }
#pragma unroll
        for (int s = 0; s < 4; s++) {
            ull va0[16], va1[16];
#pragma unroll
            for (int q = 0; q < 16; q++) { va0[q] = ba0[q]; va1[q] = ba1[q]; }
#pragma unroll 2
            for (int k = 0; k < 23; k++) {
                ull f2 = IN2(s * 23 + k);
                float2 fv = unpack2(f2);
                ull x0 = pack2(fv.x);
                ull x1 = pack2(fv.y);
                ACC16(va0, x0, OFF_COL1_WT + (88 + k) * 64 + j0);
                ACC16(va1, x1, OFF_COL1_WT + (88 + k) * 64 + j0);
            }
            const ulonglong2* cw =
                reinterpret_cast<const ulonglong2*>(sw + OFF_COL2_W + j0);
#pragma unroll
            for (int q2 = 0; q2 < 8; q2++) {
                ulonglong2 w = cw[q2];
                lacc0[s] = ffma2(w.x, relu2(va0[2 * q2]), lacc0[s]);
                lacc0[s] = ffma2(w.y, relu2(va0[2 * q2 + 1]), lacc0[s]);
                lacc1[s] = ffma2(w.x, relu2(va1[2 * q2]), lacc1[s]);
                lacc1[s] = ffma2(w.y, relu2(va1[2 * q2 + 1]), lacc1[s]);
            }
        }
    }

    // ============ color softmax + output ============
    const float col2b = sw[OFF_SC + 2];
    float l0[4], l1[4];
#pragma unroll
    for (int s = 0; s < 4; s++) {
        float2 a = unpack2(lacc0[s]);
        float2 b = unpack2(lacc1[s]);
        l0[s] = fmaxf(a.x + a.y + col2b, 0.0f);
        l1[s] = fmaxf(b.x + b.y + col2b, 0.0f);
    }
    float m0 = fmaxf(fmaxf(l0[0], l0[1]), fmaxf(l0[2], l0[3]));
    float m1 = fmaxf(fmaxf(l1[0], l1[1]), fmaxf(l1[2], l1[3]));
    float cn0[3] = {0, 0, 0}, cn1[3] = {0, 0, 0}, cd0 = 0.0f, cd1 = 0.0f;
#pragma unroll
    for (int s = 0; s < 4; s++) {
        float e0 = __expf(l0[s] - m0);
        float e1 = __expf(l1[s] - m1);
        cd0 += e0; cd1 += e1;
#pragma unroll
        for (int c = 0; c < 3; c++) {
            cn0[c] += g_T[(size_t)(s * 23 + 16 + c) * sN + p0] * e0;
            cn1[c] += g_T[(size_t)(s * 23 + 16 + c) * sN + p1] * e1;
        }
    }
    if (v0) {
        float inv = 1.0f / cd0;
        float4 o = make_float4(cn0[0] * inv, cn0[1] * inv, cn0[2] * inv, sig0);
        reinterpret_cast<float4*>(out)[pt0] = o;
    }
    if (v1) {
        float inv = 1.0f / cd1;
        float4 o = make_float4(cn1[0] * inv, cn1[1] * inv, cn1[2] * inv, sig1);
        reinterpret_cast<float4*>(out)[pt1] = o;
    }
#undef IN2
}

extern "C" void kernel_launch(void* const* d_in, const int* in_sizes, int n_in,
                              void* d_out, int out_size) {
    const float* vox     = (const float*)d_in[0];
    const float* ifrd    = (const float*)d_in[1];
    const float* view_w  = (const float*)d_in[2];
    const float* view_b  = (const float*)d_in[3];
    const float* glob_w  = (const float*)d_in[4];
    const float* glob_b  = (const float*)d_in[5];
    const float* aggw_w  = (const float*)d_in[6];
    const float* aggw_b  = (const float*)d_in[7];
    const float* fc_w    = (const float*)d_in[8];
    const float* fc_b    = (const float*)d_in[9];
    const float* lr0_w   = (const float*)d_in[10];
    const float* lr0_b   = (const float*)d_in[11];
    const float* sigma_w = (const float*)d_in[12];
    const float* sigma_b = (const float*)d_in[13];
    const float* col1_w  = (const float*)d_in[14];
    const float* col1_b  = (const float*)d_in[15];
    const float* col2_w  = (const float*)d_in[16];
    const float* col2_b  = (const float*)d_in[17];
    float* out = (float*)d_out;

    int N = in_sizes[0] / 8;
    if (N > NMAX) N = NMAX;

    cudaFuncSetAttribute(nerf_main, cudaFuncAttributeMaxDynamicSharedMemorySize, 65536);

    float* tptr = nullptr;
    float* vptr = nullptr;
    cudaGetSymbolAddress((void**)&tptr, g_T);
    cudaGetSymbolAddress((void**)&vptr, g_voxT);

    prep_kernel<<<1, 256>>>(view_w, view_b, glob_w, glob_b, aggw_w, aggw_b,
                            fc_w, fc_b, lr0_w, lr0_b, sigma_w, sigma_b,
                            col1_w, col1_b, col2_w, col2_b);

    dim3 tb(32, 8);
    dim3 tg1((N + 31) / 32, (92 + 31) / 32);
    transpose_kernel<<<tg1, tb>>>(ifrd, tptr, N, 92);
    dim3 tg2((N + 31) / 32, 1);
    transpose_kernel<<<tg2, tb>>>(vox, vptr, N, 8);

    int blocks = (N + PTSB - 1) / PTSB;
    nerf_main<<<blocks, TB, 65536>>>(out, N);
}

// round 8
// speedup vs baseline: 1.0031x; 1.0031x over previous
#include <cuda_runtime.h>
#include <math.h>

typedef unsigned long long ull;

#define NMAX 524288

// ---------------- device-global scratch ----------------
__device__ __align__(16) float g_T[92 * NMAX];     // ifrd transposed: [feat][pt]
__device__ __align__(16) float g_voxT[8 * NMAX];   // vox transposed

// Transposed weight layout (floats). wt[k*J + j], j contiguous.
#define OFF_GLOB_WT 0       // [57][32]
#define OFF_GLOB_B  1824    // [32]
#define OFF_AGGW    1856    // [32]
#define OFF_FC_WT   1888    // [32][16]
#define OFF_FC_B    2400    // [16]
#define OFF_LR0_WT  2416    // [24][64]
#define OFF_LR0_B   3952    // [64]
#define OFF_SIGMA_W 4016    // [64]
#define OFF_COL1_WT 4080    // [111][64]
#define OFF_COL1_B  11184   // [64]
#define OFF_COL2_W  11248   // [64]
#define OFF_VIEW_WT 11312   // [4][19]
#define OFF_VIEW_B  11388   // [19]
#define OFF_SC      11407   // aggw_b, sigma_b, col2_b
#define WT_TOTAL    11410

__device__ __align__(16) float g_wt[WT_TOTAL + 2];

// ---------------- packed f32x2 helpers ----------------
__device__ __forceinline__ ull ffma2(ull a, ull b, ull c) {
    ull d; asm("fma.rn.f32x2 %0, %1, %2, %3;" : "=l"(d) : "l"(a), "l"(b), "l"(c));
    return d;
}
__device__ __forceinline__ ull fmul2(ull a, ull b) {
    ull d; asm("mul.rn.f32x2 %0, %1, %2;" : "=l"(d) : "l"(a), "l"(b));
    return d;
}
__device__ __forceinline__ ull fadd2(ull a, ull b) {
    ull d; asm("add.rn.f32x2 %0, %1, %2;" : "=l"(d) : "l"(a), "l"(b));
    return d;
}
__device__ __forceinline__ ull pack2(float x) {
    ull r; asm("mov.b64 %0, {%1, %1};" : "=l"(r) : "r"(__float_as_uint(x)));
    return r;
}
__device__ __forceinline__ ull pack2f(float a, float b) {
    ull r; asm("mov.b64 %0, {%1, %2};" : "=l"(r)
               : "r"(__float_as_uint(a)), "r"(__float_as_uint(b)));
    return r;
}
__device__ __forceinline__ float2 unpack2(ull v) {
    unsigned lo, hi; asm("mov.b64 {%0, %1}, %2;" : "=r"(lo), "=r"(hi) : "l"(v));
    return make_float2(__uint_as_float(lo), __uint_as_float(hi));
}
__device__ __forceinline__ ull relu2(ull v) {
    float2 f = unpack2(v);
    return pack2f(fmaxf(f.x, 0.0f), fmaxf(f.y, 0.0f));
}
__device__ __forceinline__ float halfOf(ull v, int hi) {
    float2 f = unpack2(v);
    return hi ? f.y : f.x;
}

// acc is ull[16] (32 j outputs, j-packed). xx = pack2(scalar).
#define ACC16(acc, xx, woff)                                                     \
    {                                                                            \
        const ulonglong2* w2 = reinterpret_cast<const ulonglong2*>(sw + (woff)); \
        _Pragma("unroll")                                                        \
        for (int q = 0; q < 8; q++) {                                            \
            ulonglong2 ww = w2[q];                                               \
            acc[2 * q]     = ffma2(ww.x, (xx), acc[2 * q]);                      \
            acc[2 * q + 1] = ffma2(ww.y, (xx), acc[2 * q + 1]);                  \
        }                                                                        \
    }
#define ACC8(acc, xx, woff)                                                      \
    {                                                                            \
        const ulonglong2* w2 = reinterpret_cast<const ulonglong2*>(sw + (woff)); \
        _Pragma("unroll")                                                        \
        for (int q = 0; q < 4; q++) {                                            \
            ulonglong2 ww = w2[q];                                               \
            acc[2 * q]     = ffma2(ww.x, (xx), acc[2 * q]);                      \
            acc[2 * q + 1] = ffma2(ww.y, (xx), acc[2 * q + 1]);                  \
        }                                                                        \
    }
#define LOADB16(acc, off)                                                        \
    {                                                                            \
        const ulonglong2* b2 = reinterpret_cast<const ulonglong2*>(sw + (off));  \
        _Pragma("unroll")                                                        \
        for (int q = 0; q < 8; q++) {                                            \
            ulonglong2 bb = b2[q];                                               \
            acc[2 * q] = bb.x; acc[2 * q + 1] = bb.y;                            \
        }                                                                        \
    }
#define LOADB8(acc, off)                                                         \
    {                                                                            \
        const ulonglong2* b2 = reinterpret_cast<const ulonglong2*>(sw + (off));  \
        _Pragma("unroll")                                                        \
        for (int q = 0; q < 4; q++) {                                            \
            ulonglong2 bb = b2[q];                                               \
            acc[2 * q] = bb.x; acc[2 * q + 1] = bb.y;                            \
        }                                                                        \
    }

// ---------------- prep: transpose weights into g_wt ----------------
__global__ void prep_kernel(const float* __restrict__ view_w, const float* __restrict__ view_b,
                            const float* __restrict__ glob_w, const float* __restrict__ glob_b,
                            const float* __restrict__ aggw_w, const float* __restrict__ aggw_b,
                            const float* __restrict__ fc_w,   const float* __restrict__ fc_b,
                            const float* __restrict__ lr0_w,  const float* __restrict__ lr0_b,
                            const float* __restrict__ sigma_w,const float* __restrict__ sigma_b,
                            const float* __restrict__ col1_w, const float* __restrict__ col1_b,
                            const float* __restrict__ col2_w, const float* __restrict__ col2_b) {
    const int t = threadIdx.x;
    const int bs = blockDim.x;
    for (int idx = t; idx < 32 * 57; idx += bs) {
        int j = idx / 57, k = idx % 57;
        g_wt[OFF_GLOB_WT + k * 32 + j] = glob_w[idx];
    }
    for (int idx = t; idx < 32; idx += bs) {
        g_wt[OFF_GLOB_B + idx] = glob_b[idx];
        g_wt[OFF_AGGW + idx]   = aggw_w[idx];
    }
    for (int idx = t; idx < 16 * 32; idx += bs) {
        int j = idx / 32, k = idx % 32;
        g_wt[OFF_FC_WT + k * 16 + j] = fc_w[idx];
    }
    for (int idx = t; idx < 16; idx += bs) g_wt[OFF_FC_B + idx] = fc_b[idx];
    for (int idx = t; idx < 64 * 24; idx += bs) {
        int j = idx / 24, k = idx % 24;
        g_wt[OFF_LR0_WT + k * 64 + j] = lr0_w[idx];
    }
    for (int idx = t; idx < 64; idx += bs) {
        g_wt[OFF_LR0_B + idx]   = lr0_b[idx];
        g_wt[OFF_SIGMA_W + idx] = sigma_w[idx];
        g_wt[OFF_COL1_B + idx]  = col1_b[idx];
        g_wt[OFF_COL2_W + idx]  = col2_w[idx];
    }
    for (int idx = t; idx < 64 * 111; idx += bs) {
        int j = idx / 111, k = idx % 111;
        g_wt[OFF_COL1_WT + k * 64 + j] = col1_w[idx];
    }
    for (int idx = t; idx < 76; idx += bs) {
        int j = idx / 4, k = idx % 4;
        g_wt[OFF_VIEW_WT + k * 19 + j] = view_w[idx];
    }
    for (int idx = t; idx < 19; idx += bs) g_wt[OFF_VIEW_B + idx] = view_b[idx];
    if (t == 0) {
        g_wt[OFF_SC + 0] = aggw_b[0];
        g_wt[OFF_SC + 1] = sigma_b[0];
        g_wt[OFF_SC + 2] = col2_b[0];
    }
}

// ---------------- input transpose: [rows][cols] -> [cols][rows] ----------------
__global__ void transpose_kernel(const float* __restrict__ in, float* __restrict__ outp,
                                 int rows, int cols) {
    __shared__ float tile[32][33];
    const int c0 = blockIdx.y * 32;
    const long long r0 = (long long)blockIdx.x * 32;
    const int tx = threadIdx.x, ty = threadIdx.y;
#pragma unroll
    for (int i = 0; i < 32; i += 8) {
        long long r = r0 + ty + i;
        int c = c0 + tx;
        if (r < rows && c < cols) tile[ty + i][tx] = in[r * cols + c];
    }
    __syncthreads();
#pragma unroll
    for (int i = 0; i < 32; i += 8) {
        int c = c0 + ty + i;
        long long r = r0 + tx;
        if (r < rows && c < cols) outp[(size_t)c * rows + r] = tile[tx][ty + i];
    }
}

// ---------------- main kernel ----------------
#define TB 128
#define PTSB 256   // points per block (P=2)

__global__ void __launch_bounds__(TB)
nerf_main(float* __restrict__ out, int N) {
    extern __shared__ char dynsmem[];
    ull* sbuf = (ull*)dynsmem;                 // 32*256 ull = 64KB thread-private scratch
    __shared__ __align__(16) float sw[WT_TOTAL + 2];

    // stage weights (coalesced from pre-transposed g_wt)
    for (int idx = threadIdx.x; idx < WT_TOTAL; idx += TB) sw[idx] = g_wt[idx];
    __syncthreads();

    const int t = threadIdx.x;
    const int base = blockIdx.x * PTSB;
    const int pt0 = base + t;
    const int pt1 = base + 128 + t;
    const bool v0 = pt0 < N;
    const bool v1 = pt1 < N;
    const size_t p0 = (size_t)(v0 ? pt0 : 0);
    const size_t p1 = (size_t)(v1 ? pt1 : 0);
    const size_t sN = (size_t)N;

#define IN2(f) pack2f(g_T[(size_t)(f) * sN + p0], g_T[(size_t)(f) * sN + p1])

    // ============ Phase A: dirs, stats, gf_base (spilled to sbuf) ============
    ull dirs[4][4];
#pragma unroll
    for (int s = 0; s < 4; s++)
#pragma unroll
        for (int c = 0; c < 4; c++) dirs[s][c] = IN2(s * 23 + 19 + c);

    {
        ull gfb0[16], gfb1[16];
        LOADB16(gfb0, OFF_GLOB_B);
#pragma unroll
        for (int q = 0; q < 16; q++) gfb1[q] = gfb0[q];

        const ull c4n = pack2(-4.0f);
        const ull third = pack2(1.0f / 3.0f);
        const ull quarter = pack2(0.25f);

#pragma unroll 2
        for (int k = 0; k < 19; k++) {
            ull sum2 = 0ull, sq2 = 0ull;
#pragma unroll
            for (int s = 0; s < 4; s++) {
                ull a = pack2(sw[OFF_VIEW_B + k]);
                a = ffma2(pack2(sw[OFF_VIEW_WT + 0 * 19 + k]), dirs[s][0], a);
                a = ffma2(pack2(sw[OFF_VIEW_WT + 1 * 19 + k]), dirs[s][1], a);
                a = ffma2(pack2(sw[OFF_VIEW_WT + 2 * 19 + k]), dirs[s][2], a);
                a = ffma2(pack2(sw[OFF_VIEW_WT + 3 * 19 + k]), dirs[s][3], a);
                a = relu2(a);
                ull f = fadd2(IN2(s * 23 + k), a);
                sum2 = fadd2(sum2, f);
                sq2 = ffma2(f, f, sq2);
            }
            ull m2 = fmul2(sum2, quarter);
            ull vr2 = fmul2(ffma2(m2, fmul2(m2, c4n), sq2), third);
            float2 mf = unpack2(m2), vf = unpack2(vr2);

            ull x0 = pack2(vf.x), x1 = pack2(vf.y);
            ACC16(gfb0, x0, OFF_GLOB_WT + (19 + k) * 32);
            ACC16(gfb1, x1, OFF_GLOB_WT + (19 + k) * 32);
            x0 = pack2(mf.x); x1 = pack2(mf.y);
            ACC16(gfb0, x0, OFF_GLOB_WT + (38 + k) * 32);
            ACC16(gfb1, x1, OFF_GLOB_WT + (38 + k) * 32);
        }
        // spill gf_base to thread-private smem scratch
#pragma unroll
        for (int q = 0; q < 16; q++) {
            sbuf[q * 256 + t] = gfb0[q];
            sbuf[q * 256 + 128 + t] = gfb1[q];
        }
    }

    // ============ Phase B: per-view glob + online softmax agg ============
    ull num0[16], num1[16];
#pragma unroll
    for (int q = 0; q < 16; q++) { num0[q] = 0ull; num1[q] = 0ull; }
    float dsum0 = 0.0f, dsum1 = 0.0f, mmax0 = -1e30f, mmax1 = -1e30f;
    const float aggb = sw[OFF_SC + 0];

#pragma unroll
    for (int s = 0; s < 4; s++) {
        ull gf0[16], gf1[16];
#pragma unroll
        for (int q = 0; q < 16; q++) {
            gf0[q] = sbuf[q * 256 + t];
            gf1[q] = sbuf[q * 256 + 128 + t];
        }
#pragma unroll 2
        for (int k = 0; k < 19; k++) {
            ull a = pack2(sw[OFF_VIEW_B + k]);
            a = ffma2(pack2(sw[OFF_VIEW_WT + 0 * 19 + k]), dirs[s][0], a);
            a = ffma2(pack2(sw[OFF_VIEW_WT + 1 * 19 + k]), dirs[s][1], a);
            a = ffma2(pack2(sw[OFF_VIEW_WT + 2 * 19 + k]), dirs[s][2], a);
            a = ffma2(pack2(sw[OFF_VIEW_WT + 3 * 19 + k]), dirs[s][3], a);
            a = relu2(a);
            ull f = fadd2(IN2(s * 23 + k), a);
            float2 fi = unpack2(f);
            ull x0 = pack2(fi.x), x1 = pack2(fi.y);
            ACC16(gf0, x0, OFF_GLOB_WT + k * 32);
            ACC16(gf1, x1, OFF_GLOB_WT + k * 32);
        }
        // relu + agg dot (j-packed)
        ull la0 = 0ull, la1 = 0ull;
        {
            const ulonglong2* aw = reinterpret_cast<const ulonglong2*>(sw + OFF_AGGW);
#pragma unroll
            for (int q2 = 0; q2 < 8; q2++) {
                ulonglong2 a2 = aw[q2];
                gf0[2 * q2] = relu2(gf0[2 * q2]);
                gf0[2 * q2 + 1] = relu2(gf0[2 * q2 + 1]);
                gf1[2 * q2] = relu2(gf1[2 * q2]);
                gf1[2 * q2 + 1] = relu2(gf1[2 * q2 + 1]);
                la0 = ffma2(a2.x, gf0[2 * q2], la0);
                la0 = ffma2(a2.y, gf0[2 * q2 + 1], la0);
                la1 = ffma2(a2.x, gf1[2 * q2], la1);
                la1 = ffma2(a2.y, gf1[2 * q2 + 1], la1);
            }
        }
        float2 lf0 = unpack2(la0), lf1 = unpack2(la1);
        float l0 = fmaxf(lf0.x + lf0.y + aggb, 0.0f);
        float l1 = fmaxf(lf1.x + lf1.y + aggb, 0.0f);

        if (l0 > mmax0) {
            float c = __expf(mmax0 - l0); ull c2 = pack2(c);
            dsum0 *= c;
#pragma unroll
            for (int q = 0; q < 16; q++) num0[q] = fmul2(num0[q], c2);
            mmax0 = l0;
        }
        {
            float e = __expf(l0 - mmax0); dsum0 += e; ull e2 = pack2(e);
#pragma unroll
            for (int q = 0; q < 16; q++) num0[q] = ffma2(gf0[q], e2, num0[q]);
        }
        if (l1 > mmax1) {
            float c = __expf(mmax1 - l1); ull c2 = pack2(c);
            dsum1 *= c;
#pragma unroll
            for (int q = 0; q < 16; q++) num1[q] = fmul2(num1[q], c2);
            mmax1 = l1;
        }
        {
            float e = __expf(l1 - mmax1); dsum1 += e; ull e2 = pack2(e);
#pragma unroll
            for (int q = 0; q < 16; q++) num1[q] = ffma2(gf1[q], e2, num1[q]);
        }
    }

    // ============ fc: 32 -> 16, build vif[2][24] ============
    float vif0[24], vif1[24];
    {
        float inv0 = 1.0f / dsum0, inv1 = 1.0f / dsum1;
        ull fa0[8], fa1[8];
        LOADB8(fa0, OFF_FC_B);
#pragma unroll
        for (int q = 0; q < 8; q++) fa1[q] = fa0[q];
#pragma unroll 4
        for (int k = 0; k < 32; k++) {
            ull x0 = pack2(halfOf(num0[k >> 1], k & 1) * inv0);
            ull x1 = pack2(halfOf(num1[k >> 1], k & 1) * inv1);
            ACC8(fa0, x0, OFF_FC_WT + k * 16);
            ACC8(fa1, x1, OFF_FC_WT + k * 16);
        }
#pragma unroll
        for (int c = 0; c < 8; c++) {
            vif0[c] = g_voxT[(size_t)c * sN + p0];
            vif1[c] = g_voxT[(size_t)c * sN + p1];
        }
#pragma unroll
        for (int j = 0; j < 16; j++) {
            vif0[8 + j] = fmaxf(halfOf(fa0[j >> 1], j & 1), 0.0f);
            vif1[8 + j] = fmaxf(halfOf(fa1[j >> 1], j & 1), 0.0f);
        }
    }

    // ============ lr0: 24 -> 64 (two j-tiles), relu, sigma partial, x->sbuf ====
    ull siga0 = 0ull, siga1 = 0ull;
#pragma unroll
    for (int jt = 0; jt < 2; jt++) {
        const int j0 = jt * 32;
        ull xa0[16], xa1[16];
        LOADB16(xa0, OFF_LR0_B + j0);
#pragma unroll
        for (int q = 0; q < 16; q++) xa1[q] = xa0[q];
#pragma unroll 4
        for (int k = 0; k < 24; k++) {
            ull x0 = pack2(vif0[k]);
            ull x1 = pack2(vif1[k]);
            ACC16(xa0, x0, OFF_LR0_WT + k * 64 + j0);
            ACC16(xa1, x1, OFF_LR0_WT + k * 64 + j0);
        }
        const ulonglong2* swg = reinterpret_cast<const ulonglong2*>(sw + OFF_SIGMA_W + j0);
#pragma unroll
        for (int q2 = 0; q2 < 8; q2++) {
            ulonglong2 w = swg[q2];
            ull r0a = relu2(xa0[2 * q2]);
            ull r0b = relu2(xa0[2 * q2 + 1]);
            ull r1a = relu2(xa1[2 * q2]);
            ull r1b = relu2(xa1[2 * q2 + 1]);
            siga0 = ffma2(w.x, r0a, siga0);
            siga0 = ffma2(w.y, r0b, siga0);
            siga1 = ffma2(w.x, r1a, siga1);
            siga1 = ffma2(w.y, r1b, siga1);
            sbuf[(jt * 16 + 2 * q2) * 256 + t] = r0a;
            sbuf[(jt * 16 + 2 * q2 + 1) * 256 + t] = r0b;
            sbuf[(jt * 16 + 2 * q2) * 256 + 128 + t] = r1a;
            sbuf[(jt * 16 + 2 * q2 + 1) * 256 + 128 + t] = r1b;
        }
    }
    float sig0, sig1;
    {
        float2 s0 = unpack2(siga0), s1 = unpack2(siga1);
        float l0 = s0.x + s0.y + sw[OFF_SC + 1];
        float l1 = s1.x + s1.y + sw[OFF_SC + 1];
        sig0 = (l0 > 20.0f) ? l0 : log1pf(expf(l0));
        sig1 = (l1 > 20.0f) ? l1 : log1pf(expf(l1));
    }

    // ============ col1 (j-tiled) + col2 partial logits ============
    ull lacc0[4], lacc1[4];
#pragma unroll
    for (int s = 0; s < 4; s++) { lacc0[s] = 0ull; lacc1[s] = 0ull; }
    const float* sbf = (const float*)sbuf;  // x as scalars: idx = (k>>1)*512 + ptl*2 + (k&1)

#pragma unroll
    for (int jt = 0; jt < 2; jt++) {
        const int j0 = jt * 32;
        ull ba0[16], ba1[16];
        LOADB16(ba0, OFF_COL1_B + j0);
#pragma unroll
        for (int q = 0; q < 16; q++) ba1[q] = ba0[q];
#pragma unroll 2
        for (int k = 0; k < 64; k++) {
            float xv0 = sbf[(k >> 1) * 512 + t * 2 + (k & 1)];
            float xv1 = sbf[(k >> 1) * 512 + (128 + t) * 2 + (k & 1)];
            ull x0 = pack2(xv0);
            ull x1 = pack2(xv1);
            ACC16(ba0, x0, OFF_COL1_WT + k * 64 + j0);
            ACC16(ba1, x1, OFF_COL1_WT + k * 64 + j0);
        }
#pragma unroll 2
        for (int k = 0; k < 24; k++) {
            ull x0 = pack2(vif0[k]);
            ull x1 = pack2(vif1[k]);
            ACC16(ba0, x0, OFF_COL1_WT + (64 + k) * 64 + j0);
            ACC16(ba1, x1, OFF_COL1_WT + (64 + k) * 64 + j0);
        }
#pragma unroll
        for (int s = 0; s < 4; s++) {
            ull va0[16], va1[16];
#pragma unroll
            for (int q = 0; q < 16; q++) { va0[q] = ba0[q]; va1[q] = ba1[q]; }
#pragma unroll 2
            for (int k = 0; k < 23; k++) {
                ull f2 = IN2(s * 23 + k);
                float2 fv = unpack2(f2);
                ull x0 = pack2(fv.x);
                ull x1 = pack2(fv.y);
                ACC16(va0, x0, OFF_COL1_WT + (88 + k) * 64 + j0);
                ACC16(va1, x1, OFF_COL1_WT + (88 + k) * 64 + j0);
            }
            const ulonglong2* cw =
                reinterpret_cast<const ulonglong2*>(sw + OFF_COL2_W + j0);
#pragma unroll
            for (int q2 = 0; q2 < 8; q2++) {
                ulonglong2 w = cw[q2];
                lacc0[s] = ffma2(w.x, relu2(va0[2 * q2]), lacc0[s]);
                lacc0[s] = ffma2(w.y, relu2(va0[2 * q2 + 1]), lacc0[s]);
                lacc1[s] = ffma2(w.x, relu2(va1[2 * q2]), lacc1[s]);
                lacc1[s] = ffma2(w.y, relu2(va1[2 * q2 + 1]), lacc1[s]);
            }
        }
    }

    // ============ color softmax + output ============
    const float col2b = sw[OFF_SC + 2];
    float l0[4], l1[4];
#pragma unroll
    for (int s = 0; s < 4; s++) {
        float2 a = unpack2(lacc0[s]);
        float2 b = unpack2(lacc1[s]);
        l0[s] = fmaxf(a.x + a.y + col2b, 0.0f);
        l1[s] = fmaxf(b.x + b.y + col2b, 0.0f);
    }
    float m0 = fmaxf(fmaxf(l0[0], l0[1]), fmaxf(l0[2], l0[3]));
    float m1 = fmaxf(fmaxf(l1[0], l1[1]), fmaxf(l1[2], l1[3]));
    float cn0[3] = {0, 0, 0}, cn1[3] = {0, 0, 0}, cd0 = 0.0f, cd1 = 0.0f;
#pragma unroll
    for (int s = 0; s < 4; s++) {
        float e0 = __expf(l0[s] - m0);
        float e1 = __expf(l1[s] - m1);
        cd0 += e0; cd1 += e1;
#pragma unroll
        for (int c = 0; c < 3; c++) {
            cn0[c] += g_T[(size_t)(s * 23 + 16 + c) * sN + p0] * e0;
            cn1[c] += g_T[(size_t)(s * 23 + 16 + c) * sN + p1] * e1;
        }
    }
    if (v0) {
        float inv = 1.0f / cd0;
        float4 o = make_float4(cn0[0] * inv, cn0[1] * inv, cn0[2] * inv, sig0);
        reinterpret_cast<float4*>(out)[pt0] = o;
    }
    if (v1) {
        float inv = 1.0f / cd1;
        float4 o = make_float4(cn1[0] * inv, cn1[1] * inv, cn1[2] * inv, sig1);
        reinterpret_cast<float4*>(out)[pt1] = o;
    }
#undef IN2
}

extern "C" void kernel_launch(void* const* d_in, const int* in_sizes, int n_in,
                              void* d_out, int out_size) {
    const float* vox     = (const float*)d_in[0];
    const float* ifrd    = (const float*)d_in[1];
    const float* view_w  = (const float*)d_in[2];
    const float* view_b  = (const float*)d_in[3];
    const float* glob_w  = (const float*)d_in[4];
    const float* glob_b  = (const float*)d_in[5];
    const float* aggw_w  = (const float*)d_in[6];
    const float* aggw_b  = (const float*)d_in[7];
    const float* fc_w    = (const float*)d_in[8];
    const float* fc_b    = (const float*)d_in[9];
    const float* lr0_w   = (const float*)d_in[10];
    const float* lr0_b   = (const float*)d_in[11];
    const float* sigma_w = (const float*)d_in[12];
    const float* sigma_b = (const float*)d_in[13];
    const float* col1_w  = (const float*)d_in[14];
    const float* col1_b  = (const float*)d_in[15];
    const float* col2_w  = (const float*)d_in[16];
    const float* col2_b  = (const float*)d_in[17];
    float* out = (float*)d_out;

    int N = in_sizes[0] / 8;
    if (N > NMAX) N = NMAX;

    cudaFuncSetAttribute(nerf_main, cudaFuncAttributeMaxDynamicSharedMemorySize, 65536);

    float* tptr = nullptr;
    float* vptr = nullptr;
    cudaGetSymbolAddress((void**)&tptr, g_T);
    cudaGetSymbolAddress((void**)&vptr, g_voxT);

    prep_kernel<<<1, 256>>>(view_w, view_b, glob_w, glob_b, aggw_w, aggw_b,
                            fc_w, fc_b, lr0_w, lr0_b, sigma_w, sigma_b,
                            col1_w, col1_b, col2_w, col2_b);

    dim3 tb(32, 8);
    dim3 tg1((N + 31) / 32, (92 + 31) / 32);
    transpose_kernel<<<tg1, tb>>>(ifrd, tptr, N, 92);
    dim3 tg2((N + 31) / 32, 1);
    transpose_kernel<<<tg2, tb>>>(vox, vptr, N, 8);

    int blocks = (N + PTSB - 1) / PTSB;
    nerf_main<<<blocks, TB, 65536>>>(out, N);
}

// round 9
// speedup vs baseline: 1.0036x; 1.0005x over previous
#include <cuda_runtime.h>
#include <math.h>

typedef unsigned long long ull;

#define NMAX 524288

// ---------------- device-global scratch ----------------
__device__ __align__(16) float g_T[92 * NMAX];     // ifrd transposed: [feat][pt]
__device__ __align__(16) float g_voxT[8 * NMAX];   // vox transposed

// Transposed weight layout (floats). wt[k*J + j], j contiguous.
#define OFF_GLOB_WT 0       // [57][32]
#define OFF_GLOB_B  1824    // [32]
#define OFF_AGGW    1856    // [32]
#define OFF_FC_WT   1888    // [32][16]
#define OFF_FC_B    2400    // [16]
#define OFF_LR0_WT  2416    // [24][64]
#define OFF_LR0_B   3952    // [64]
#define OFF_SIGMA_W 4016    // [64]
#define OFF_COL1_WT 4080    // [111][64]
#define OFF_COL1_B  11184   // [64]
#define OFF_COL2_W  11248   // [64]
#define OFF_VIEW_WT 11312   // [4][19]
#define OFF_VIEW_B  11388   // [19]
#define OFF_SC      11407   // aggw_b, sigma_b, col2_b
#define WT_TOTAL    11410

__device__ __align__(16) float g_wt[WT_TOTAL + 2];

// ---------------- packed f32x2 helpers ----------------
__device__ __forceinline__ ull ffma2(ull a, ull b, ull c) {
    ull d; asm("fma.rn.f32x2 %0, %1, %2, %3;" : "=l"(d) : "l"(a), "l"(b), "l"(c));
    return d;
}
__device__ __forceinline__ ull fmul2(ull a, ull b) {
    ull d; asm("mul.rn.f32x2 %0, %1, %2;" : "=l"(d) : "l"(a), "l"(b));
    return d;
}
__device__ __forceinline__ ull fadd2(ull a, ull b) {
    ull d; asm("add.rn.f32x2 %0, %1, %2;" : "=l"(d) : "l"(a), "l"(b));
    return d;
}
__device__ __forceinline__ ull pack2(float x) {
    ull r; asm("mov.b64 %0, {%1, %1};" : "=l"(r) : "r"(__float_as_uint(x)));
    return r;
}
__device__ __forceinline__ ull pack2f(float a, float b) {
    ull r; asm("mov.b64 %0, {%1, %2};" : "=l"(r)
               : "r"(__float_as_uint(a)), "r"(__float_as_uint(b)));
    return r;
}
__device__ __forceinline__ float2 unpack2(ull v) {
    unsigned lo, hi; asm("mov.b64 {%0, %1}, %2;" : "=r"(lo), "=r"(hi) : "l"(v));
    return make_float2(__uint_as_float(lo), __uint_as_float(hi));
}
__device__ __forceinline__ ull relu2(ull v) {
    float2 f = unpack2(v);
    return pack2f(fmaxf(f.x, 0.0f), fmaxf(f.y, 0.0f));
}
__device__ __forceinline__ float halfOf(ull v, int hi) {
    float2 f = unpack2(v);
    return hi ? f.y : f.x;
}

// acc is ull[16] (32 j outputs, j-packed). xx = pack2(scalar).
#define ACC16(acc, xx, woff)                                                     \
    {                                                                            \
        const ulonglong2* w2 = reinterpret_cast<const ulonglong2*>(sw + (woff)); \
        _Pragma("unroll")                                                        \
        for (int q = 0; q < 8; q++) {                                            \
            ulonglong2 ww = w2[q];                                               \
            acc[2 * q]     = ffma2(ww.x, (xx), acc[2 * q]);                      \
            acc[2 * q + 1] = ffma2(ww.y, (xx), acc[2 * q + 1]);                  \
        }                                                                        \
    }
#define ACC8(acc, xx, woff)                                                      \
    {                                                                            \
        const ulonglong2* w2 = reinterpret_cast<const ulonglong2*>(sw + (woff)); \
        _Pragma("unroll")                                                        \
        for (int q = 0; q < 4; q++) {                                            \
            ulonglong2 ww = w2[q];                                               \
            acc[2 * q]     = ffma2(ww.x, (xx), acc[2 * q]);                      \
            acc[2 * q + 1] = ffma2(ww.y, (xx), acc[2 * q + 1]);                  \
        }                                                                        \
    }
#define LOADB16(acc, off)                                                        \
    {                                                                            \
        const ulonglong2* b2 = reinterpret_cast<const ulonglong2*>(sw + (off));  \
        _Pragma("unroll")                                                        \
        for (int q = 0; q < 8; q++) {                                            \
            ulonglong2 bb = b2[q];                                               \
            acc[2 * q] = bb.x; acc[2 * q + 1] = bb.y;                            \
        }                                                                        \
    }
#define LOADB8(acc, off)                                                         \
    {                                                                            \
        const ulonglong2* b2 = reinterpret_cast<const ulonglong2*>(sw + (off));  \
        _Pragma("unroll")                                                        \
        for (int q = 0; q < 4; q++) {                                            \
            ulonglong2 bb = b2[q];                                               \
            acc[2 * q] = bb.x; acc[2 * q + 1] = bb.y;                            \
        }                                                                        \
    }

// ---------------- prep: transpose weights into g_wt ----------------
__global__ void prep_kernel(const float* __restrict__ view_w, const float* __restrict__ view_b,
                            const float* __restrict__ glob_w, const float* __restrict__ glob_b,
                            const float* __restrict__ aggw_w, const float* __restrict__ aggw_b,
                            const float* __restrict__ fc_w,   const float* __restrict__ fc_b,
                            const float* __restrict__ lr0_w,  const float* __restrict__ lr0_b,
                            const float* __restrict__ sigma_w,const float* __restrict__ sigma_b,
                            const float* __restrict__ col1_w, const float* __restrict__ col1_b,
                            const float* __restrict__ col2_w, const float* __restrict__ col2_b) {
    const int t = threadIdx.x;
    const int bs = blockDim.x;
    for (int idx = t; idx < 32 * 57; idx += bs) {
        int j = idx / 57, k = idx % 57;
        g_wt[OFF_GLOB_WT + k * 32 + j] = glob_w[idx];
    }
    for (int idx = t; idx < 32; idx += bs) {
        g_wt[OFF_GLOB_B + idx] = glob_b[idx];
        g_wt[OFF_AGGW + idx]   = aggw_w[idx];
    }
    for (int idx = t; idx < 16 * 32; idx += bs) {
        int j = idx / 32, k = idx % 32;
        g_wt[OFF_FC_WT + k * 16 + j] = fc_w[idx];
    }
    for (int idx = t; idx < 16; idx += bs) g_wt[OFF_FC_B + idx] = fc_b[idx];
    for (int idx = t; idx < 64 * 24; idx += bs) {
        int j = idx / 24, k = idx % 24;
        g_wt[OFF_LR0_WT + k * 64 + j] = lr0_w[idx];
    }
    for (int idx = t; idx < 64; idx += bs) {
        g_wt[OFF_LR0_B + idx]   = lr0_b[idx];
        g_wt[OFF_SIGMA_W + idx] = sigma_w[idx];
        g_wt[OFF_COL1_B + idx]  = col1_b[idx];
        g_wt[OFF_COL2_W + idx]  = col2_w[idx];
    }
    for (int idx = t; idx < 64 * 111; idx += bs) {
        int j = idx / 111, k = idx % 111;
        g_wt[OFF_COL1_WT + k * 64 + j] = col1_w[idx];
    }
    for (int idx = t; idx < 76; idx += bs) {
        int j = idx / 4, k = idx % 4;
        g_wt[OFF_VIEW_WT + k * 19 + j] = view_w[idx];
    }
    for (int idx = t; idx < 19; idx += bs) g_wt[OFF_VIEW_B + idx] = view_b[idx];
    if (t == 0) {
        g_wt[OFF_SC + 0] = aggw_b[0];
        g_wt[OFF_SC + 1] = sigma_b[0];
        g_wt[OFF_SC + 2] = col2_b[0];
    }
}

// ---------------- input transpose: [rows][cols] -> [cols][rows] ----------------
__global__ void transpose_kernel(const float* __restrict__ in, float* __restrict__ outp,
                                 int rows, int cols) {
    __shared__ float tile[32][33];
    const int c0 = blockIdx.y * 32;
    const long long r0 = (long long)blockIdx.x * 32;
    const int tx = threadIdx.x, ty = threadIdx.y;
#pragma unroll
    for (int i = 0; i < 32; i += 8) {
        long long r = r0 + ty + i;
        int c = c0 + tx;
        if (r < rows && c < cols) tile[ty + i][tx] = in[r * cols + c];
    }
    __syncthreads();
#pragma unroll
    for (int i = 0; i < 32; i += 8) {
        int c = c0 + ty + i;
        long long r = r0 + tx;
        if (r < rows && c < cols) outp[(size_t)c * rows + r] = tile[tx][ty + i];
    }
}

// ---------------- main kernel ----------------
#define TB 128
#define PTSB 256   // points per block (P=2)

__global__ void __launch_bounds__(TB)
nerf_main(float* __restrict__ out, int N) {
    extern __shared__ char dynsmem[];
    ull* sbuf = (ull*)dynsmem;                 // 32*256 ull = 64KB thread-private scratch
    __shared__ __align__(16) float sw[WT_TOTAL + 2];

    // stage weights (coalesced from pre-transposed g_wt)
    for (int idx = threadIdx.x; idx < WT_TOTAL; idx += TB) sw[idx] = g_wt[idx];
    __syncthreads();

    const int t = threadIdx.x;
    const int base = blockIdx.x * PTSB;
    const int pt0 = base + t;
    const int pt1 = base + 128 + t;
    const bool v0 = pt0 < N;
    const bool v1 = pt1 < N;
    const size_t p0 = (size_t)(v0 ? pt0 : 0);
    const size_t p1 = (size_t)(v1 ? pt1 : 0);
    const size_t sN = (size_t)N;

#define IN2(f) pack2f(g_T[(size_t)(f) * sN + p0], g_T[(size_t)(f) * sN + p1])

    // ============ Phase A: dirs, stats, gf_base (spilled to sbuf) ============
    ull dirs[4][4];
#pragma unroll
    for (int s = 0; s < 4; s++)
#pragma unroll
        for (int c = 0; c < 4; c++) dirs[s][c] = IN2(s * 23 + 19 + c);

    {
        ull gfb0[16], gfb1[16];
        LOADB16(gfb0, OFF_GLOB_B);
#pragma unroll
        for (int q = 0; q < 16; q++) gfb1[q] = gfb0[q];

        const ull c4n = pack2(-4.0f);
        const ull third = pack2(1.0f / 3.0f);
        const ull quarter = pack2(0.25f);

#pragma unroll 2
        for (int k = 0; k < 19; k++) {
            ull sum2 = 0ull, sq2 = 0ull;
#pragma unroll
            for (int s = 0; s < 4; s++) {
                ull a = pack2(sw[OFF_VIEW_B + k]);
                a = ffma2(pack2(sw[OFF_VIEW_WT + 0 * 19 + k]), dirs[s][0], a);
                a = ffma2(pack2(sw[OFF_VIEW_WT + 1 * 19 + k]), dirs[s][1], a);
                a = ffma2(pack2(sw[OFF_VIEW_WT + 2 * 19 + k]), dirs[s][2], a);
                a = ffma2(pack2(sw[OFF_VIEW_WT + 3 * 19 + k]), dirs[s][3], a);
                a = relu2(a);
                ull f = fadd2(IN2(s * 23 + k), a);
                sum2 = fadd2(sum2, f);
                sq2 = ffma2(f, f, sq2);
            }
            ull m2 = fmul2(sum2, quarter);
            ull vr2 = fmul2(ffma2(m2, fmul2(m2, c4n), sq2), third);
            float2 mf = unpack2(m2), vf = unpack2(vr2);

            ull x0 = pack2(vf.x), x1 = pack2(vf.y);
            ACC16(gfb0, x0, OFF_GLOB_WT + (19 + k) * 32);
            ACC16(gfb1, x1, OFF_GLOB_WT + (19 + k) * 32);
            x0 = pack2(mf.x); x1 = pack2(mf.y);
            ACC16(gfb0, x0, OFF_GLOB_WT + (38 + k) * 32);
            ACC16(gfb1, x1, OFF_GLOB_WT + (38 + k) * 32);
        }
        // spill gf_base to thread-private smem scratch
#pragma unroll
        for (int q = 0; q < 16; q++) {
            sbuf[q * 256 + t] = gfb0[q];
            sbuf[q * 256 + 128 + t] = gfb1[q];
        }
    }

    // ============ Phase B: per-view glob + online softmax agg ============
    ull num0[16], num1[16];
#pragma unroll
    for (int q = 0; q < 16; q++) { num0[q] = 0ull; num1[q] = 0ull; }
    float dsum0 = 0.0f, dsum1 = 0.0f, mmax0 = -1e30f, mmax1 = -1e30f;
    const float aggb = sw[OFF_SC + 0];

#pragma unroll
    for (int s = 0; s < 4; s++) {
        ull gf0[16], gf1[16];
#pragma unroll
        for (int q = 0; q < 16; q++) {
            gf0[q] = sbuf[q * 256 + t];
            gf1[q] = sbuf[q * 256 + 128 + t];
        }
#pragma unroll 2
        for (int k = 0; k < 19; k++) {
            ull a = pack2(sw[OFF_VIEW_B + k]);
            a = ffma2(pack2(sw[OFF_VIEW_WT + 0 * 19 + k]), dirs[s][0], a);
            a = ffma2(pack2(sw[OFF_VIEW_WT + 1 * 19 + k]), dirs[s][1], a);
            a = ffma2(pack2(sw[OFF_VIEW_WT + 2 * 19 + k]), dirs[s][2], a);
            a = ffma2(pack2(sw[OFF_VIEW_WT + 3 * 19 + k]), dirs[s][3], a);
            a = relu2(a);
            ull f = fadd2(IN2(s * 23 + k), a);
            float2 fi = unpack2(f);
            ull x0 = pack2(fi.x), x1 = pack2(fi.y);
            ACC16(gf0, x0, OFF_GLOB_WT + k * 32);
            ACC16(gf1, x1, OFF_GLOB_WT + k * 32);
        }
        // relu + agg dot (j-packed)
        ull la0 = 0ull, la1 = 0ull;
        {
            const ulonglong2* aw = reinterpret_cast<const ulonglong2*>(sw + OFF_AGGW);
#pragma unroll
            for (int q2 = 0; q2 < 8; q2++) {
                ulonglong2 a2 = aw[q2];
                gf0[2 * q2] = relu2(gf0[2 * q2]);
                gf0[2 * q2 + 1] = relu2(gf0[2 * q2 + 1]);
                gf1[2 * q2] = relu2(gf1[2 * q2]);
                gf1[2 * q2 + 1] = relu2(gf1[2 * q2 + 1]);
                la0 = ffma2(a2.x, gf0[2 * q2], la0);
                la0 = ffma2(a2.y, gf0[2 * q2 + 1], la0);
                la1 = ffma2(a2.x, gf1[2 * q2], la1);
                la1 = ffma2(a2.y, gf1[2 * q2 + 1], la1);
            }
        }
        float2 lf0 = unpack2(la0), lf1 = unpack2(la1);
        float l0 = fmaxf(lf0.x + lf0.y + aggb, 0.0f);
        float l1 = fmaxf(lf1.x + lf1.y + aggb, 0.0f);

        if (l0 > mmax0) {
            float c = __expf(mmax0 - l0); ull c2 = pack2(c);
            dsum0 *= c;
#pragma unroll
            for (int q = 0; q < 16; q++) num0[q] = fmul2(num0[q], c2);
            mmax0 = l0;
        }
        {
            float e = __expf(l0 - mmax0); dsum0 += e; ull e2 = pack2(e);
#pragma unroll
            for (int q = 0; q < 16; q++) num0[q] = ffma2(gf0[q], e2, num0[q]);
        }
        if (l1 > mmax1) {
            float c = __expf(mmax1 - l1); ull c2 = pack2(c);
            dsum1 *= c;
#pragma unroll
            for (int q = 0; q < 16; q++) num1[q] = fmul2(num1[q], c2);
            mmax1 = l1;
        }
        {
            float e = __expf(l1 - mmax1); dsum1 += e; ull e2 = pack2(e);
#pragma unroll
            for (int q = 0; q < 16; q++) num1[q] = ffma2(gf1[q], e2, num1[q]);
        }
    }

    // ============ fc: 32 -> 16, build vif[2][24] ============
    float vif0[24], vif1[24];
    {
        float inv0 = 1.0f / dsum0, inv1 = 1.0f / dsum1;
        ull fa0[8], fa1[8];
        LOADB8(fa0, OFF_FC_B);
#pragma unroll
        for (int q = 0; q < 8; q++) fa1[q] = fa0[q];
#pragma unroll 4
        for (int k = 0; k < 32; k++) {
            ull x0 = pack2(halfOf(num0[k >> 1], k & 1) * inv0);
            ull x1 = pack2(halfOf(num1[k >> 1], k & 1) * inv1);
            ACC8(fa0, x0, OFF_FC_WT + k * 16);
            ACC8(fa1, x1, OFF_FC_WT + k * 16);
        }
#pragma unroll
        for (int c = 0; c < 8; c++) {
            vif0[c] = g_voxT[(size_t)c * sN + p0];
            vif1[c] = g_voxT[(size_t)c * sN + p1];
        }
#pragma unroll
        for (int j = 0; j < 16; j++) {
            vif0[8 + j] = fmaxf(halfOf(fa0[j >> 1], j & 1), 0.0f);
            vif1[8 + j] = fmaxf(halfOf(fa1[j >> 1], j & 1), 0.0f);
        }
    }

    // ============ lr0: 24 -> 64 (two j-tiles), relu, sigma partial, x->sbuf ====
    ull siga0 = 0ull, siga1 = 0ull;
#pragma unroll
    for (int jt = 0; jt < 2; jt++) {
        const int j0 = jt * 32;
        ull xa0[16], xa1[16];
        LOADB16(xa0, OFF_LR0_B + j0);
#pragma unroll
        for (int q = 0; q < 16; q++) xa1[q] = xa0[q];
#pragma unroll 4
        for (int k = 0; k < 24; k++) {
            ull x0 = pack2(vif0[k]);
            ull x1 = pack2(vif1[k]);
            ACC16(xa0, x0, OFF_LR0_WT + k * 64 + j0);
            ACC16(xa1, x1, OFF_LR0_WT + k * 64 + j0);
        }
        const ulonglong2* swg = reinterpret_cast<const ulonglong2*>(sw + OFF_SIGMA_W + j0);
#pragma unroll
        for (int q2 = 0; q2 < 8; q2++) {
            ulonglong2 w = swg[q2];
            ull r0a = relu2(xa0[2 * q2]);
            ull r0b = relu2(xa0[2 * q2 + 1]);
            ull r1a = relu2(xa1[2 * q2]);
            ull r1b = relu2(xa1[2 * q2 + 1]);
            siga0 = ffma2(w.x, r0a, siga0);
            siga0 = ffma2(w.y, r0b, siga0);
            siga1 = ffma2(w.x, r1a, siga1);
            siga1 = ffma2(w.y, r1b, siga1);
            sbuf[(jt * 16 + 2 * q2) * 256 + t] = r0a;
            sbuf[(jt * 16 + 2 * q2 + 1) * 256 + t] = r0b;
            sbuf[(jt * 16 + 2 * q2) * 256 + 128 + t] = r1a;
            sbuf[(jt * 16 + 2 * q2 + 1) * 256 + 128 + t] = r1b;
        }
    }
    float sig0, sig1;
    {
        float2 s0 = unpack2(siga0), s1 = unpack2(siga1);
        float l0 = s0.x + s0.y + sw[OFF_SC + 1];
        float l1 = s1.x + s1.y + sw[OFF_SC + 1];
        sig0 = (l0 > 20.0f) ? l0 : log1pf(expf(l0));
        sig1 = (l1 > 20.0f) ? l1 : log1pf(expf(l1));
    }

    // ============ col1 (j-tiled) + col2 partial logits ============
    ull lacc0[4], lacc1[4];
#pragma unroll
    for (int s = 0; s < 4; s++) { lacc0[s] = 0ull; lacc1[s] = 0ull; }
    const float* sbf = (const float*)sbuf;  // x as scalars: idx = (k>>1)*512 + ptl*2 + (k&1)

#pragma unroll
    for (int jt = 0; jt < 2; jt++) {
        const int j0 = jt * 32;
        ull ba0[16], ba1[16];
        LOADB16(ba0, OFF_COL1_B + j0);
#pragma unroll
        for (int q = 0; q < 16; q++) ba1[q] = ba0[q];
#pragma unroll 2
        for (int k = 0; k < 64; k++) {
            float xv0 = sbf[(k >> 1) * 512 + t * 2 + (k & 1)];
            float xv1 = sbf[(k >> 1) * 512 + (128 + t) * 2 + (k & 1)];
            ull x0 = pack2(xv0);
            ull x1 = pack2(xv1);
            ACC16(ba0, x0, OFF_COL1_WT + k * 64 + j0);
            ACC16(ba1, x1, OFF_COL1_WT + k * 64 + j0);
        }
#pragma unroll 2
        for (int k = 0; k < 24; k++) {
            ull x0 = pack2(vif0[k]);
            ull x1 = pack2(vif1[k]);
            ACC16(ba0, x0, OFF_COL1_WT + (64 + k) * 64 + j0);
            ACC16(ba1, x1, OFF_COL1_WT + (64 + k) * 64 + j0);
        }
#pragma unroll
        for (int s = 0; s < 4; s++) {
            ull va0[16], va1[16];
#pragma unroll
            for (int q = 0; q < 16; q++) { va0[q] = ba0[q]; va1[q] = ba1[q]; }
#pragma unroll 2
            for (int k = 0; k < 23; k++) {
                ull f2 = IN2(s * 23 + k);
                float2 fv = unpack2(f2);
                ull x0 = pack2(fv.x);
                ull x1 = pack2(fv.y);
                ACC16(va0, x0, OFF_COL1_WT + (88 + k) * 64 + j0);
                ACC16(va1, x1, OFF_COL1_WT + (88 + k) * 64 + j0);
            }
            const ulonglong2* cw =
                reinterpret_cast<const ulonglong2*>(sw + OFF_COL2_W + j0);
#pragma unroll
            for (int q2 = 0; q2 < 8; q2++) {
                ulonglong2 w = cw[q2];
                lacc0[s] = ffma2(w.x, relu2(va0[2 * q2]), lacc0[s]);
                lacc0[s] = ffma2(w.y, relu2(va0[2 * q2 + 1]), lacc0[s]);
                lacc1[s] = ffma2(w.x, relu2(va1[2 * q2]), lacc1[s]);
                lacc1[s] = ffma2(w.y, relu2(va1[2 * q2 + 1]), lacc1[s]);
            }
        }
    }

    // ============ color softmax + output ============
    const float col2b = sw[OFF_SC + 2];
    float l0[4], l1[4];
#pragma unroll
    for (int s = 0; s < 4; s++) {
        float2 a = unpack2(lacc0[s]);
        float2 b = unpack2(lacc1[s]);
        l0[s] = fmaxf(a.x + a.y + col2b, 0.0f);
        l1[s] = fmaxf(b.x + b.y + col2b, 0.0f);
    }
    float m0 = fmaxf(fmaxf(l0[0], l0[1]), fmaxf(l0[2], l0[3]));
    float m1 = fmaxf(fmaxf(l1[0], l1[1]), fmaxf(l1[2], l1[3]));
    float cn0[3] = {0, 0, 0}, cn1[3] = {0, 0, 0}, cd0 = 0.0f, cd1 = 0.0f;
#pragma unroll
    for (int s = 0; s < 4; s++) {
        float e0 = __expf(l0[s] - m0);
        float e1 = __expf(l1[s] - m1);
        cd0 += e0; cd1 += e1;
#pragma unroll
        for (int c = 0; c < 3; c++) {
            cn0[c] += g_T[(size_t)(s * 23 + 16 + c) * sN + p0] * e0;
            cn1[c] += g_T[(size_t)(s * 23 + 16 + c) * sN + p1] * e1;
        }
    }
    if (v0) {
        float inv = 1.0f / cd0;
        float4 o = make_float4(cn0[0] * inv, cn0[1] * inv, cn0[2] * inv, sig0);
        reinterpret_cast<float4*>(out)[pt0] = o;
    }
    if (v1) {
        float inv = 1.0f / cd1;
        float4 o = make_float4(cn1[0] * inv, cn1[1] * inv, cn1[2] * inv, sig1);
        reinterpret_cast<float4*>(out)[pt1] = o;
    }
#undef IN2
}

extern "C" void kernel_launch(void* const* d_in, const int* in_sizes, int n_in,
                              void* d_out, int out_size) {
    const float* vox     = (const float*)d_in[0];
    const float* ifrd    = (const float*)d_in[1];
    const float* view_w  = (const float*)d_in[2];
    const float* view_b  = (const float*)d_in[3];
    const float* glob_w  = (const float*)d_in[4];
    const float* glob_b  = (const float*)d_in[5];
    const float* aggw_w  = (const float*)d_in[6];
    const float* aggw_b  = (const float*)d_in[7];
    const float* fc_w    = (const float*)d_in[8];
    const float* fc_b    = (const float*)d_in[9];
    const float* lr0_w   = (const float*)d_in[10];
    const float* lr0_b   = (const float*)d_in[11];
    const float* sigma_w = (const float*)d_in[12];
    const float* sigma_b = (const float*)d_in[13];
    const float* col1_w  = (const float*)d_in[14];
    const float* col1_b  = (const float*)d_in[15];
    const float* col2_w  = (const float*)d_in[16];
    const float* col2_b  = (const float*)d_in[17];
    float* out = (float*)d_out;

    int N = in_sizes[0] / 8;
    if (N > NMAX) N = NMAX;

    cudaFuncSetAttribute(nerf_main, cudaFuncAttributeMaxDynamicSharedMemorySize, 65536);

    float* tptr = nullptr;
    float* vptr = nullptr;
    cudaGetSymbolAddress((void**)&tptr, g_T);
    cudaGetSymbolAddress((void**)&vptr, g_voxT);

    prep_kernel<<<1, 256>>>(view_w, view_b, glob_w, glob_b, aggw_w, aggw_b,
                            fc_w, fc_b, lr0_w, lr0_b, sigma_w, sigma_b,
                            col1_w, col1_b, col2_w, col2_b);

    dim3 tb(32, 8);
    dim3 tg1((N + 31) / 32, (92 + 31) / 32);
    transpose_kernel<<<tg1, tb>>>(ifrd, tptr, N, 92);
    dim3 tg2((N + 31) / 32, 1);
    transpose_kernel<<<tg2, tb>>>(vox, vptr, N, 8);

    int blocks = (N + PTSB - 1) / PTSB;
    nerf_main<<<blocks, TB, 65536>>>(out, N);
}